// round 2
// baseline (speedup 1.0000x reference)
#include <cuda_runtime.h>
#include <math.h>

// ---------------- problem constants ----------------
#define TROWS 131072          // B * H * W = 32 * 4096
#define DIMC  384
#define HIDC  1536
#define QKVC  1152
#define NHEAD 12
#define HDIM  32
#define NTOK  64              // tokens per window
#define NWIN  2048            // 32 * 64 windows

// ---------------- scratch (device globals; no allocation) ----------------
__device__ float g_qkv[150994944];   // TROWS * 1152
__device__ float g_attn[50331648];   // TROWS * 384
__device__ float g_tmp[50331648];    // TROWS * 384
__device__ float g_x1[50331648];     // TROWS * 384
__device__ float g_hid[201326592];   // TROWS * 1536
__device__ float g_bias16[NHEAD * 225];
__device__ float g_scale[NHEAD];
__device__ float g_qkvbias[QKVC];

// ---------------- prep: CPB table, head scales, qkv bias ----------------
__device__ __forceinline__ float cpb_norm(int c) {
    // t = c/7*8 ; sign(t)*log2(|t|+1)/log2(8)
    float t = (float)c * (8.0f / 7.0f);
    float s = (t > 0.f) ? 1.f : ((t < 0.f) ? -1.f : 0.f);
    return s * log2f(fabsf(t) + 1.0f) * (1.0f / 3.0f);
}

__global__ void prep_kernel(const float* __restrict__ ls,
                            const float* __restrict__ w1,
                            const float* __restrict__ b1,
                            const float* __restrict__ w2,
                            const float* __restrict__ qb,
                            const float* __restrict__ vb)
{
    int tid = threadIdx.x;
    for (int i = tid; i < QKVC; i += 256) {
        float v = 0.f;
        if (i < 384) v = qb[i];
        else if (i >= 768) v = vb[i - 768];
        g_qkvbias[i] = v;
    }
    if (tid < NHEAD) g_scale[tid] = expf(fminf(ls[tid], 4.6051701859880914f)); // ln(100)
    if (tid < 225) {
        int i = tid / 15, j = tid % 15;
        float f0 = cpb_norm(j - 7);   // coords entry 0
        float f1 = cpb_norm(i - 7);   // coords entry 1
        float acc[NHEAD];
        #pragma unroll
        for (int h = 0; h < NHEAD; h++) acc[h] = 0.f;
        for (int u = 0; u < 512; u++) {
            float hu = fmaf(f0, w1[u], fmaf(f1, w1[512 + u], b1[u]));
            hu = fmaxf(hu, 0.f);
            #pragma unroll
            for (int h = 0; h < NHEAD; h++) acc[h] = fmaf(hu, w2[u * 12 + h], acc[h]);
        }
        #pragma unroll
        for (int h = 0; h < NHEAD; h++)
            g_bias16[h * 225 + tid] = 16.f / (1.f + expf(-acc[h]));
    }
}

// ---------------- attention: one (window, head) per block ----------------
__global__ __launch_bounds__(64) void attn_kernel(const float* __restrict__ qkv,
                                                  float* __restrict__ out)
{
    __shared__ float kn[64][33];
    __shared__ float vs[64][33];
    __shared__ float bia[225];
    __shared__ int   lab[64];

    int blk  = blockIdx.x;
    int head = blk % NHEAD;
    int w    = blk / NHEAD;
    int b    = w >> 6;
    int win  = w & 63;
    int wh = win >> 3, ww = win & 7;
    int t = threadIdx.x;
    int r = t >> 3, c = t & 7;
    int hp = wh * 8 + r, wp = ww * 8 + c;          // position in shifted image
    int sh = (hp + 4) & 63, sw = (wp + 4) & 63;    // source position in x
    size_t row = (size_t)b * 4096 + (size_t)sh * 64 + sw;
    const float* base = qkv + row * QKVC + head * HDIM;

    int lh = (hp < 56) ? 0 : ((hp < 60) ? 1 : 2);
    int lw = (wp < 56) ? 0 : ((wp < 60) ? 1 : 2);
    lab[t] = lh * 3 + lw;

    for (int i = t; i < 225; i += 64) bia[i] = g_bias16[head * 225 + i];

    float qreg[HDIM];
    {
        float tmp[HDIM];
        float nk = 0.f;
        #pragma unroll
        for (int d4 = 0; d4 < 8; d4++) {
            float4 v4 = *(const float4*)(base + 384 + d4 * 4);
            tmp[d4*4+0] = v4.x; tmp[d4*4+1] = v4.y; tmp[d4*4+2] = v4.z; tmp[d4*4+3] = v4.w;
        }
        #pragma unroll
        for (int d = 0; d < HDIM; d++) nk = fmaf(tmp[d], tmp[d], nk);
        float invk = 1.0f / sqrtf(nk);
        #pragma unroll
        for (int d = 0; d < HDIM; d++) kn[t][d] = tmp[d] * invk;

        #pragma unroll
        for (int d4 = 0; d4 < 8; d4++) {
            float4 v4 = *(const float4*)(base + 768 + d4 * 4);
            vs[t][d4*4+0] = v4.x; vs[t][d4*4+1] = v4.y; vs[t][d4*4+2] = v4.z; vs[t][d4*4+3] = v4.w;
        }

        float nq = 0.f;
        #pragma unroll
        for (int d4 = 0; d4 < 8; d4++) {
            float4 v4 = *(const float4*)(base + d4 * 4);
            qreg[d4*4+0] = v4.x; qreg[d4*4+1] = v4.y; qreg[d4*4+2] = v4.z; qreg[d4*4+3] = v4.w;
        }
        #pragma unroll
        for (int d = 0; d < HDIM; d++) nq = fmaf(qreg[d], qreg[d], nq);
        float invq = g_scale[head] / sqrtf(nq);    // fold cosine-attn scale into q
        #pragma unroll
        for (int d = 0; d < HDIM; d++) qreg[d] *= invq;
    }
    __syncthreads();

    float lg[NTOK];
    float mx = -1e30f;
    int myl = lab[t];
    for (int t2 = 0; t2 < NTOK; t2++) {
        float acc = 0.f;
        #pragma unroll
        for (int d = 0; d < HDIM; d++) acc = fmaf(qreg[d], kn[t2][d], acc);
        int r2 = t2 >> 3, c2 = t2 & 7;
        acc += bia[(c - c2 + 7) * 15 + (r - r2 + 7)];
        if (myl != lab[t2]) acc -= 100.f;
        lg[t2] = acc;
        mx = fmaxf(mx, acc);
    }
    float ssum = 0.f;
    for (int t2 = 0; t2 < NTOK; t2++) {
        lg[t2] = __expf(lg[t2] - mx);
        ssum += lg[t2];
    }
    float isum = 1.0f / ssum;
    for (int t2 = 0; t2 < NTOK; t2++) lg[t2] *= isum;

    float* orow = out + row * DIMC + head * HDIM;  // scatter undoes shift+partition
    for (int d = 0; d < HDIM; d++) {
        float acc = 0.f;
        for (int t2 = 0; t2 < NTOK; t2++) acc = fmaf(lg[t2], vs[t2][d], acc);
        orow[d] = acc;
    }
}

// ---------------- SGEMM: C[M,N] = A[M,K]@B[K,N] + bias (opt. GELU) ----------------
template<int ACT>
__global__ __launch_bounds__(256) void sgemm_kernel(
    const float* __restrict__ A, const float* __restrict__ B,
    const float* __restrict__ bias, float* __restrict__ C,
    int M, int N, int K)
{
    __shared__ float As[8][128];
    __shared__ float Bs[8][128];
    int tid = threadIdx.x;
    int bx = blockIdx.x, by = blockIdx.y;
    int tx = tid & 15, ty = tid >> 4;
    int arow = tid >> 1, acol = (tid & 1) << 2;
    int brow = tid >> 5, bcol = (tid & 31) << 2;

    const float* Ap = A + (size_t)(by * 128 + arow) * K + acol;
    const float* Bp = B + (size_t)brow * N + bx * 128 + bcol;

    float acc[8][8];
    #pragma unroll
    for (int i = 0; i < 8; i++)
        #pragma unroll
        for (int j = 0; j < 8; j++) acc[i][j] = 0.f;

    int nk = K >> 3;
    for (int kk = 0; kk < nk; kk++) {
        float4 a4 = *(const float4*)Ap;
        float4 b4 = *(const float4*)Bp;
        As[acol + 0][arow] = a4.x;
        As[acol + 1][arow] = a4.y;
        As[acol + 2][arow] = a4.z;
        As[acol + 3][arow] = a4.w;
        *(float4*)&Bs[brow][bcol] = b4;
        __syncthreads();
        #pragma unroll
        for (int k = 0; k < 8; k++) {
            float ar[8], br[8];
            #pragma unroll
            for (int i = 0; i < 8; i++) ar[i] = As[k][ty * 8 + i];
            #pragma unroll
            for (int j = 0; j < 8; j++) br[j] = Bs[k][tx * 8 + j];
            #pragma unroll
            for (int i = 0; i < 8; i++)
                #pragma unroll
                for (int j = 0; j < 8; j++)
                    acc[i][j] = fmaf(ar[i], br[j], acc[i][j]);
        }
        __syncthreads();
        Ap += 8;
        Bp += (size_t)8 * N;
    }

    #pragma unroll
    for (int i = 0; i < 8; i++) {
        int row = by * 128 + ty * 8 + i;
        #pragma unroll
        for (int j0 = 0; j0 < 8; j0 += 4) {
            int col = bx * 128 + tx * 8 + j0;
            float4 o;
            float* po = (float*)&o;
            #pragma unroll
            for (int j = 0; j < 4; j++) {
                float v = acc[i][j0 + j] + bias[col + j];
                if (ACT == 1) {  // tanh-approx GELU (JAX default)
                    float inner = fmaf(0.044715f * v * v, v, v);
                    float th = tanhf(0.7978845608028654f * inner);
                    v = 0.5f * v * (1.f + th);
                }
                po[j] = v;
            }
            *(float4*)(C + (size_t)row * N + col) = o;
        }
    }
}

// ---------------- residual + LayerNorm (warp per row) ----------------
__global__ __launch_bounds__(256) void add_ln_kernel(
    const float* __restrict__ res, const float* __restrict__ y,
    const float* __restrict__ sc, const float* __restrict__ bi,
    float* __restrict__ out)
{
    int row  = blockIdx.x * 8 + (threadIdx.x >> 5);
    int lane = threadIdx.x & 31;
    const float* yr = y + (size_t)row * DIMC;
    float v[12];
    float s = 0.f, s2 = 0.f;
    #pragma unroll
    for (int k = 0; k < 12; k++) {
        v[k] = yr[lane + k * 32];
        s += v[k];
        s2 = fmaf(v[k], v[k], s2);
    }
    #pragma unroll
    for (int o = 16; o > 0; o >>= 1) {
        s  += __shfl_xor_sync(0xffffffffu, s,  o);
        s2 += __shfl_xor_sync(0xffffffffu, s2, o);
    }
    float mu  = s * (1.f / 384.f);
    float var = s2 * (1.f / 384.f) - mu * mu;
    float inv = rsqrtf(var + 1e-6f);
    const float* rr = res + (size_t)row * DIMC;
    float* orow = out + (size_t)row * DIMC;
    #pragma unroll
    for (int k = 0; k < 12; k++) {
        int col = lane + k * 32;
        orow[col] = rr[col] + (v[k] - mu) * inv * sc[col] + bi[col];
    }
}

// ---------------- launch ----------------
extern "C" void kernel_launch(void* const* d_in, const int* in_sizes, int n_in,
                              void* d_out, int out_size)
{
    (void)in_sizes; (void)n_in; (void)out_size;
    const float* x        = (const float*)d_in[0];
    const float* qkv_w    = (const float*)d_in[1];
    const float* q_bias   = (const float*)d_in[2];
    const float* v_bias   = (const float*)d_in[3];
    const float* lscale   = (const float*)d_in[4];
    const float* cpb_w1   = (const float*)d_in[5];
    const float* cpb_b1   = (const float*)d_in[6];
    const float* cpb_w2   = (const float*)d_in[7];
    const float* proj_w   = (const float*)d_in[8];
    const float* proj_b   = (const float*)d_in[9];
    const float* n1s      = (const float*)d_in[10];
    const float* n1b      = (const float*)d_in[11];
    const float* fc1_w    = (const float*)d_in[12];
    const float* fc1_b    = (const float*)d_in[13];
    const float* fc2_w    = (const float*)d_in[14];
    const float* fc2_b    = (const float*)d_in[15];
    const float* n2s      = (const float*)d_in[16];
    const float* n2b      = (const float*)d_in[17];
    float* out = (float*)d_out;

    float *qkv, *attn, *tmp, *x1, *hid, *qbias;
    cudaGetSymbolAddress((void**)&qkv,   g_qkv);
    cudaGetSymbolAddress((void**)&attn,  g_attn);
    cudaGetSymbolAddress((void**)&tmp,   g_tmp);
    cudaGetSymbolAddress((void**)&x1,    g_x1);
    cudaGetSymbolAddress((void**)&hid,   g_hid);
    cudaGetSymbolAddress((void**)&qbias, g_qkvbias);

    prep_kernel<<<1, 256>>>(lscale, cpb_w1, cpb_b1, cpb_w2, q_bias, v_bias);

    // qkv = x @ qkv_w + [q_bias, 0, v_bias]
    {
        dim3 grid(QKVC / 128, TROWS / 128);
        sgemm_kernel<0><<<grid, 256>>>(x, qkv_w, qbias, qkv, TROWS, QKVC, DIMC);
    }

    // windowed cosine attention (shift folded into gather/scatter)
    attn_kernel<<<NWIN * NHEAD, 64>>>(qkv, attn);

    // proj
    {
        dim3 grid(DIMC / 128, TROWS / 128);
        sgemm_kernel<0><<<grid, 256>>>(attn, proj_w, proj_b, tmp, TROWS, DIMC, DIMC);
    }

    // x1 = x + LN(proj_out)
    add_ln_kernel<<<TROWS / 8, 256>>>(x, tmp, n1s, n1b, x1);

    // hid = gelu(x1 @ fc1_w + fc1_b)
    {
        dim3 grid(HIDC / 128, TROWS / 128);
        sgemm_kernel<1><<<grid, 256>>>(x1, fc1_w, fc1_b, hid, TROWS, HIDC, DIMC);
    }

    // y = hid @ fc2_w + fc2_b
    {
        dim3 grid(DIMC / 128, TROWS / 128);
        sgemm_kernel<0><<<grid, 256>>>(hid, fc2_w, fc2_b, tmp, TROWS, DIMC, HIDC);
    }

    // out = x1 + LN(y)
    add_ln_kernel<<<TROWS / 8, 256>>>(x1, tmp, n2s, n2b, out);
}

// round 4
// speedup vs baseline: 2.3103x; 2.3103x over previous
#include <cuda_runtime.h>
#include <math.h>

// ---------------- problem constants ----------------
#define TROWS 131072          // B * H * W = 32 * 4096
#define DIMC  384
#define HIDC  1536
#define QKVC  1152
#define NHEAD 12
#define HDIM  32
#define NTOK  64              // tokens per window
#define NWIN  2048            // 32 * 64 windows

// ---------------- scratch (device globals; no allocation) ----------------
__device__ float g_qkv[150994944];   // TROWS * 1152
__device__ float g_attn[50331648];   // TROWS * 384
__device__ float g_tmp[50331648];    // TROWS * 384
__device__ float g_x1[50331648];     // TROWS * 384
__device__ float g_hid[201326592];   // TROWS * 1536
__device__ float g_bias16[NHEAD * 225];
__device__ float g_scale[NHEAD];
__device__ float g_qkvbias[QKVC];

// ---------------- prep: CPB table, head scales, qkv bias ----------------
__device__ __forceinline__ float cpb_norm(int c) {
    float t = (float)c * (8.0f / 7.0f);
    float s = (t > 0.f) ? 1.f : ((t < 0.f) ? -1.f : 0.f);
    return s * log2f(fabsf(t) + 1.0f) * (1.0f / 3.0f);
}

__global__ void prep_kernel(const float* __restrict__ ls,
                            const float* __restrict__ w1,
                            const float* __restrict__ b1,
                            const float* __restrict__ w2,
                            const float* __restrict__ qb,
                            const float* __restrict__ vb)
{
    int tid = threadIdx.x;
    for (int i = tid; i < QKVC; i += 256) {
        float v = 0.f;
        if (i < 384) v = qb[i];
        else if (i >= 768) v = vb[i - 768];
        g_qkvbias[i] = v;
    }
    if (tid < NHEAD) g_scale[tid] = expf(fminf(ls[tid], 4.6051701859880914f)); // ln(100)
    if (tid < 225) {
        int i = tid / 15, j = tid % 15;
        float f0 = cpb_norm(j - 7);
        float f1 = cpb_norm(i - 7);
        float acc[NHEAD];
        #pragma unroll
        for (int h = 0; h < NHEAD; h++) acc[h] = 0.f;
        for (int u = 0; u < 512; u++) {
            float hu = fmaf(f0, w1[u], fmaf(f1, w1[512 + u], b1[u]));
            hu = fmaxf(hu, 0.f);
            #pragma unroll
            for (int h = 0; h < NHEAD; h++) acc[h] = fmaf(hu, w2[u * 12 + h], acc[h]);
        }
        #pragma unroll
        for (int h = 0; h < NHEAD; h++)
            g_bias16[h * 225 + tid] = 16.f / (1.f + expf(-acc[h]));
    }
}

// ---------------- attention: one (window, head) per block ----------------
__global__ __launch_bounds__(64) void attn_kernel(const float* __restrict__ qkv,
                                                  float* __restrict__ out)
{
    __shared__ float kn[64][33];
    __shared__ float vs[64][33];
    __shared__ float bia[225];
    __shared__ int   lab[64];

    int blk  = blockIdx.x;
    int head = blk % NHEAD;
    int w    = blk / NHEAD;
    int b    = w >> 6;
    int win  = w & 63;
    int wh = win >> 3, ww = win & 7;
    int t = threadIdx.x;
    int r = t >> 3, c = t & 7;
    int hp = wh * 8 + r, wp = ww * 8 + c;
    int sh = (hp + 4) & 63, sw = (wp + 4) & 63;
    size_t row = (size_t)b * 4096 + (size_t)sh * 64 + sw;
    const float* base = qkv + row * QKVC + head * HDIM;

    int lh = (hp < 56) ? 0 : ((hp < 60) ? 1 : 2);
    int lw = (wp < 56) ? 0 : ((wp < 60) ? 1 : 2);
    lab[t] = lh * 3 + lw;

    for (int i = t; i < 225; i += 64) bia[i] = g_bias16[head * 225 + i];

    float qreg[HDIM];
    {
        float tmp[HDIM];
        float nk = 0.f;
        #pragma unroll
        for (int d4 = 0; d4 < 8; d4++) {
            float4 v4 = *(const float4*)(base + 384 + d4 * 4);
            tmp[d4*4+0] = v4.x; tmp[d4*4+1] = v4.y; tmp[d4*4+2] = v4.z; tmp[d4*4+3] = v4.w;
        }
        #pragma unroll
        for (int d = 0; d < HDIM; d++) nk = fmaf(tmp[d], tmp[d], nk);
        float invk = 1.0f / sqrtf(nk);
        #pragma unroll
        for (int d = 0; d < HDIM; d++) kn[t][d] = tmp[d] * invk;

        #pragma unroll
        for (int d4 = 0; d4 < 8; d4++) {
            float4 v4 = *(const float4*)(base + 768 + d4 * 4);
            vs[t][d4*4+0] = v4.x; vs[t][d4*4+1] = v4.y; vs[t][d4*4+2] = v4.z; vs[t][d4*4+3] = v4.w;
        }

        float nq = 0.f;
        #pragma unroll
        for (int d4 = 0; d4 < 8; d4++) {
            float4 v4 = *(const float4*)(base + d4 * 4);
            qreg[d4*4+0] = v4.x; qreg[d4*4+1] = v4.y; qreg[d4*4+2] = v4.z; qreg[d4*4+3] = v4.w;
        }
        #pragma unroll
        for (int d = 0; d < HDIM; d++) nq = fmaf(qreg[d], qreg[d], nq);
        float invq = g_scale[head] / sqrtf(nq);
        #pragma unroll
        for (int d = 0; d < HDIM; d++) qreg[d] *= invq;
    }
    __syncthreads();

    float lg[NTOK];
    float mx = -1e30f;
    int myl = lab[t];
    for (int t2 = 0; t2 < NTOK; t2++) {
        float acc = 0.f;
        #pragma unroll
        for (int d = 0; d < HDIM; d++) acc = fmaf(qreg[d], kn[t2][d], acc);
        int r2 = t2 >> 3, c2 = t2 & 7;
        acc += bia[(c - c2 + 7) * 15 + (r - r2 + 7)];
        if (myl != lab[t2]) acc -= 100.f;
        lg[t2] = acc;
        mx = fmaxf(mx, acc);
    }
    float ssum = 0.f;
    for (int t2 = 0; t2 < NTOK; t2++) {
        lg[t2] = __expf(lg[t2] - mx);
        ssum += lg[t2];
    }
    float isum = 1.0f / ssum;
    for (int t2 = 0; t2 < NTOK; t2++) lg[t2] *= isum;

    float* orow = out + row * DIMC + head * HDIM;
    for (int d = 0; d < HDIM; d++) {
        float acc = 0.f;
        for (int t2 = 0; t2 < NTOK; t2++) acc = fmaf(lg[t2], vs[t2][d], acc);
        orow[d] = acc;
    }
}

// ---------------- tf32 tensor-core GEMM ----------------
// C[M,N] = A[M,K] @ B[K,N] + bias, optional tanh-GELU.
// 128x128x16 tiles, 256 threads (8 warps, 2x4), warp tile 64x32,
// mma.sync.m16n8k8 tf32, smem double-buffered with register staging.
#define BKG 16
#define ASTR 136   // padded m-stride: bank = 8*(k%4) + m%... -> conflict-free LDS

__device__ __forceinline__ unsigned f2tf32(float f) {
    unsigned u;
    asm("cvt.rna.tf32.f32 %0, %1;" : "=r"(u) : "f"(f));
    return u;
}

__device__ __forceinline__ void mma_tf32(float* d, const unsigned* a, const unsigned* b) {
    asm volatile(
        "mma.sync.aligned.m16n8k8.row.col.f32.tf32.tf32.f32 "
        "{%0,%1,%2,%3}, {%4,%5,%6,%7}, {%8,%9}, {%0,%1,%2,%3};"
        : "+f"(d[0]), "+f"(d[1]), "+f"(d[2]), "+f"(d[3])
        : "r"(a[0]), "r"(a[1]), "r"(a[2]), "r"(a[3]),
          "r"(b[0]), "r"(b[1]));
}

template<int ACT>
__global__ __launch_bounds__(256) void tgemm_kernel(
    const float* __restrict__ A, const float* __restrict__ B,
    const float* __restrict__ bias, float* __restrict__ C,
    int M, int N, int K)
{
    __shared__ unsigned As[2][BKG][ASTR];
    __shared__ unsigned Bs[2][BKG][ASTR];

    int tid = threadIdx.x;
    int lane = tid & 31, wid = tid >> 5;
    int wm = (wid & 1) * 64;       // warp m-offset in tile
    int wn = (wid >> 1) * 32;      // warp n-offset in tile
    int bm = blockIdx.y * 128, bn = blockIdx.x * 128;

    // A staging: thread loads row (tid>>1), k cols [(tid&1)*8, +8) : 2 float4
    int a_r = tid >> 1, a_k = (tid & 1) * 8;
    // B staging: thread loads k-row (tid>>4), n cols chunk: 2 float4 at (tid&15)*4 and +64
    int b_k = tid >> 4, b_c = (tid & 15) * 4;

    const float* Ap = A + (size_t)(bm + a_r) * K + a_k;
    const float* Bp = B + (size_t)b_k * N + bn + b_c;

    float acc[4][4][4];
    #pragma unroll
    for (int i = 0; i < 4; i++)
        #pragma unroll
        for (int j = 0; j < 4; j++)
            #pragma unroll
            for (int l = 0; l < 4; l++) acc[i][j][l] = 0.f;

    float4 av0, av1, bv0, bv1;

    // prologue: tile 0
    av0 = *(const float4*)Ap;
    av1 = *(const float4*)(Ap + 4);
    bv0 = *(const float4*)Bp;
    bv1 = *(const float4*)(Bp + 64);
    {
        As[0][a_k + 0][a_r] = f2tf32(av0.x);
        As[0][a_k + 1][a_r] = f2tf32(av0.y);
        As[0][a_k + 2][a_r] = f2tf32(av0.z);
        As[0][a_k + 3][a_r] = f2tf32(av0.w);
        As[0][a_k + 4][a_r] = f2tf32(av1.x);
        As[0][a_k + 5][a_r] = f2tf32(av1.y);
        As[0][a_k + 6][a_r] = f2tf32(av1.z);
        As[0][a_k + 7][a_r] = f2tf32(av1.w);
        Bs[0][b_k][b_c + 0] = f2tf32(bv0.x);
        Bs[0][b_k][b_c + 1] = f2tf32(bv0.y);
        Bs[0][b_k][b_c + 2] = f2tf32(bv0.z);
        Bs[0][b_k][b_c + 3] = f2tf32(bv0.w);
        Bs[0][b_k][64 + b_c + 0] = f2tf32(bv1.x);
        Bs[0][b_k][64 + b_c + 1] = f2tf32(bv1.y);
        Bs[0][b_k][64 + b_c + 2] = f2tf32(bv1.z);
        Bs[0][b_k][64 + b_c + 3] = f2tf32(bv1.w);
    }
    __syncthreads();

    int nk = K / BKG;
    int lk = lane & 3, lm = lane >> 2;

    for (int kt = 0; kt < nk; kt++) {
        int cur = kt & 1;
        if (kt + 1 < nk) {
            Ap += BKG;
            Bp += (size_t)BKG * N;
            av0 = *(const float4*)Ap;
            av1 = *(const float4*)(Ap + 4);
            bv0 = *(const float4*)Bp;
            bv1 = *(const float4*)(Bp + 64);
        }

        #pragma unroll
        for (int k0 = 0; k0 < BKG; k0 += 8) {
            unsigned afr[4][4], bfr[4][2];
            #pragma unroll
            for (int mi = 0; mi < 4; mi++) {
                int mb = wm + mi * 16 + lm;
                afr[mi][0] = As[cur][k0 + lk][mb];
                afr[mi][1] = As[cur][k0 + lk][mb + 8];
                afr[mi][2] = As[cur][k0 + 4 + lk][mb];
                afr[mi][3] = As[cur][k0 + 4 + lk][mb + 8];
            }
            #pragma unroll
            for (int ni = 0; ni < 4; ni++) {
                int nb = wn + ni * 8 + lm;
                bfr[ni][0] = Bs[cur][k0 + lk][nb];
                bfr[ni][1] = Bs[cur][k0 + 4 + lk][nb];
            }
            #pragma unroll
            for (int mi = 0; mi < 4; mi++)
                #pragma unroll
                for (int ni = 0; ni < 4; ni++)
                    mma_tf32(acc[mi][ni], afr[mi], bfr[ni]);
        }

        if (kt + 1 < nk) {
            int nxt = cur ^ 1;
            As[nxt][a_k + 0][a_r] = f2tf32(av0.x);
            As[nxt][a_k + 1][a_r] = f2tf32(av0.y);
            As[nxt][a_k + 2][a_r] = f2tf32(av0.z);
            As[nxt][a_k + 3][a_r] = f2tf32(av0.w);
            As[nxt][a_k + 4][a_r] = f2tf32(av1.x);
            As[nxt][a_k + 5][a_r] = f2tf32(av1.y);
            As[nxt][a_k + 6][a_r] = f2tf32(av1.z);
            As[nxt][a_k + 7][a_r] = f2tf32(av1.w);
            Bs[nxt][b_k][b_c + 0] = f2tf32(bv0.x);
            Bs[nxt][b_k][b_c + 1] = f2tf32(bv0.y);
            Bs[nxt][b_k][b_c + 2] = f2tf32(bv0.z);
            Bs[nxt][b_k][b_c + 3] = f2tf32(bv0.w);
            Bs[nxt][b_k][64 + b_c + 0] = f2tf32(bv1.x);
            Bs[nxt][b_k][64 + b_c + 1] = f2tf32(bv1.y);
            Bs[nxt][b_k][64 + b_c + 2] = f2tf32(bv1.z);
            Bs[nxt][b_k][64 + b_c + 3] = f2tf32(bv1.w);
        }
        __syncthreads();
    }

    // epilogue: c0/c1 -> (m=lm, n=2*lk, 2*lk+1); c2/c3 -> (m=lm+8, ...)
    #pragma unroll
    for (int mi = 0; mi < 4; mi++) {
        #pragma unroll
        for (int part = 0; part < 2; part++) {
            int row = bm + wm + mi * 16 + lm + part * 8;
            #pragma unroll
            for (int ni = 0; ni < 4; ni++) {
                int col = bn + wn + ni * 8 + lk * 2;
                float v0 = acc[mi][ni][part * 2 + 0] + bias[col];
                float v1 = acc[mi][ni][part * 2 + 1] + bias[col + 1];
                if (ACT == 1) {
                    float i0 = fmaf(0.044715f * v0 * v0, v0, v0);
                    v0 = 0.5f * v0 * (1.f + tanhf(0.7978845608028654f * i0));
                    float i1 = fmaf(0.044715f * v1 * v1, v1, v1);
                    v1 = 0.5f * v1 * (1.f + tanhf(0.7978845608028654f * i1));
                }
                float2 o = make_float2(v0, v1);
                *(float2*)(C + (size_t)row * N + col) = o;
            }
        }
    }
}

// ---------------- residual + LayerNorm (warp per row) ----------------
__global__ __launch_bounds__(256) void add_ln_kernel(
    const float* __restrict__ res, const float* __restrict__ y,
    const float* __restrict__ sc, const float* __restrict__ bi,
    float* __restrict__ out)
{
    int row  = blockIdx.x * 8 + (threadIdx.x >> 5);
    int lane = threadIdx.x & 31;
    const float* yr = y + (size_t)row * DIMC;
    float v[12];
    float s = 0.f, s2 = 0.f;
    #pragma unroll
    for (int k = 0; k < 12; k++) {
        v[k] = yr[lane + k * 32];
        s += v[k];
        s2 = fmaf(v[k], v[k], s2);
    }
    #pragma unroll
    for (int o = 16; o > 0; o >>= 1) {
        s  += __shfl_xor_sync(0xffffffffu, s,  o);
        s2 += __shfl_xor_sync(0xffffffffu, s2, o);
    }
    float mu  = s * (1.f / 384.f);
    float var = s2 * (1.f / 384.f) - mu * mu;
    float inv = rsqrtf(var + 1e-6f);
    const float* rr = res + (size_t)row * DIMC;
    float* orow = out + (size_t)row * DIMC;
    #pragma unroll
    for (int k = 0; k < 12; k++) {
        int col = lane + k * 32;
        orow[col] = rr[col] + (v[k] - mu) * inv * sc[col] + bi[col];
    }
}

// ---------------- launch ----------------
extern "C" void kernel_launch(void* const* d_in, const int* in_sizes, int n_in,
                              void* d_out, int out_size)
{
    (void)in_sizes; (void)n_in; (void)out_size;
    const float* x        = (const float*)d_in[0];
    const float* qkv_w    = (const float*)d_in[1];
    const float* q_bias   = (const float*)d_in[2];
    const float* v_bias   = (const float*)d_in[3];
    const float* lscale   = (const float*)d_in[4];
    const float* cpb_w1   = (const float*)d_in[5];
    const float* cpb_b1   = (const float*)d_in[6];
    const float* cpb_w2   = (const float*)d_in[7];
    const float* proj_w   = (const float*)d_in[8];
    const float* proj_b   = (const float*)d_in[9];
    const float* n1s      = (const float*)d_in[10];
    const float* n1b      = (const float*)d_in[11];
    const float* fc1_w    = (const float*)d_in[12];
    const float* fc1_b    = (const float*)d_in[13];
    const float* fc2_w    = (const float*)d_in[14];
    const float* fc2_b    = (const float*)d_in[15];
    const float* n2s      = (const float*)d_in[16];
    const float* n2b      = (const float*)d_in[17];
    float* out = (float*)d_out;

    float *qkv, *attn, *tmp, *x1, *hid, *qbias;
    cudaGetSymbolAddress((void**)&qkv,   g_qkv);
    cudaGetSymbolAddress((void**)&attn,  g_attn);
    cudaGetSymbolAddress((void**)&tmp,   g_tmp);
    cudaGetSymbolAddress((void**)&x1,    g_x1);
    cudaGetSymbolAddress((void**)&hid,   g_hid);
    cudaGetSymbolAddress((void**)&qbias, g_qkvbias);

    prep_kernel<<<1, 256>>>(lscale, cpb_w1, cpb_b1, cpb_w2, q_bias, v_bias);

    // qkv = x @ qkv_w + [q_bias, 0, v_bias]
    {
        dim3 grid(QKVC / 128, TROWS / 128);
        tgemm_kernel<0><<<grid, 256>>>(x, qkv_w, qbias, qkv, TROWS, QKVC, DIMC);
    }

    // windowed cosine attention (shift folded into gather/scatter)
    attn_kernel<<<NWIN * NHEAD, 64>>>(qkv, attn);

    // proj
    {
        dim3 grid(DIMC / 128, TROWS / 128);
        tgemm_kernel<0><<<grid, 256>>>(attn, proj_w, proj_b, tmp, TROWS, DIMC, DIMC);
    }

    // x1 = x + LN(proj_out)
    add_ln_kernel<<<TROWS / 8, 256>>>(x, tmp, n1s, n1b, x1);

    // hid = gelu(x1 @ fc1_w + fc1_b)
    {
        dim3 grid(HIDC / 128, TROWS / 128);
        tgemm_kernel<1><<<grid, 256>>>(x1, fc1_w, fc1_b, hid, TROWS, HIDC, DIMC);
    }

    // y = hid @ fc2_w + fc2_b
    {
        dim3 grid(DIMC / 128, TROWS / 128);
        tgemm_kernel<0><<<grid, 256>>>(hid, fc2_w, fc2_b, tmp, TROWS, DIMC, HIDC);
    }

    // out = x1 + LN(y)
    add_ln_kernel<<<TROWS / 8, 256>>>(x1, tmp, n2s, n2b, out);
}